// round 1
// baseline (speedup 1.0000x reference)
#include <cuda_runtime.h>
#include <cstdint>

// IMDCT fused kernel:
//   out[b, s*256+k] = (1/128) * ( sum_f K[k,f]*spec[b,f,s] + sum_f K[k+256,f]*spec[b,f,s-1] )
// spec: [16, 1, 256, 4096] f32 (f-major, t contiguous), kernels: [512, 256] f32, out: [16, 1048832] f32
//
// Block = 256 threads (thread k = kernel row / offset-in-segment), owns NSEG=32 output
// segments => 33 spec columns (zero-padded edges). Accumulate per-column streams:
//   accK[j] : column c = s0-1+j contributes to segment c   (via K[k, f])
//   accB[j] : column c = s0-1+j contributes to segment c+1 (via K[k+256, f])
// Columns are paired into 64-bit registers and reduced with fma.rn.f32x2 (packed fp32 FMA).

#define NFREQ      256
#define T_FRAMES   4096
#define NSEG       32          // output segments per block
#define NCOL_PAD   36          // 33 real columns + zero pad, multiple of 4 for 16B loads
#define FT         32          // kernel f-tile width
#define KPAD       33          // kernel tile row pad (conflict-free LDS both phases)
#define L_OUT      1048832     // (4096-1)*256 + 512
#define NSEG_TOTAL 4097

#define FMA2(acc, a, v) \
    asm("fma.rn.f32x2 %0, %1, %2, %0;" : "+l"(acc) : "l"(a), "l"(v))

__global__ __launch_bounds__(256, 2)
void imdct_fused_kernel(const float* __restrict__ spec,
                        const float* __restrict__ kernels,
                        float* __restrict__ out)
{
    extern __shared__ float smem[];
    float* tileK   = smem;                  // [512][KPAD]  (67,584 B)
    float* spec_sm = smem + 512 * KPAD;     // [256][NCOL_PAD] (36,864 B)

    const int tid = threadIdx.x;
    const int k   = tid;
    const int b   = blockIdx.y;
    const int s0  = blockIdx.x * NSEG;

    const uint32_t spec_base = (uint32_t)__cvta_generic_to_shared(spec_sm);

    // ---- Load spec columns c = s0-1 .. s0+32 (zero-fill out-of-range) ----
    const float* specB = spec + (size_t)b * NFREQ * T_FRAMES;
    for (int idx = tid; idx < NFREQ * NCOL_PAD; idx += 256) {
        int f = idx / NCOL_PAD;
        int j = idx - f * NCOL_PAD;
        int c = s0 - 1 + j;
        float v = 0.0f;
        if (j < 34 && c >= 0 && c < T_FRAMES)
            v = specB[(size_t)f * T_FRAMES + c];
        spec_sm[idx] = v;
    }

    // ---- Accumulators: 17 column-pairs per stream, packed f32x2 ----
    unsigned long long accK[17], accB[17];
    #pragma unroll
    for (int p = 0; p < 17; p++) { accK[p] = 0ull; accB[p] = 0ull; }

    const int rowA = k * KPAD;
    const int rowB = (k + 256) * KPAD;
    const float4* kg = reinterpret_cast<const float4*>(kernels);

    for (int tile = 0; tile < NFREQ / FT; tile++) {
        __syncthreads();   // previous tile fully consumed (also orders spec stores on iter 0)
        // Load kernel tile [512][FT] into smem, row-padded to KPAD.
        // Gmem: warp covers 4 rows x 8 float4 (128B contiguous per row) => coalesced.
        // Smem: per store-slot lanes hit banks (kk + 4*f4 + d) % 32, all distinct.
        #pragma unroll
        for (int it = 0; it < 16; it++) {
            int i  = tid + it * 256;
            int kk = i >> 3;
            int f4 = i & 7;
            float4 v = kg[kk * 64 + tile * 8 + f4];
            float* dst = &tileK[kk * KPAD + f4 * 4];
            dst[0] = v.x; dst[1] = v.y; dst[2] = v.z; dst[3] = v.w;
        }
        __syncthreads();

        #pragma unroll 8
        for (int ff = 0; ff < FT; ff++) {
            // per-thread kernel weights (lanes k consecutive -> conflict-free with KPAD=33)
            float ka = tileK[rowA + ff];
            float kb = tileK[rowB + ff];
            unsigned long long ka2, kb2;
            asm("mov.b64 %0, {%1, %1};" : "=l"(ka2) : "r"(__float_as_uint(ka)));
            asm("mov.b64 %0, {%1, %1};" : "=l"(kb2) : "r"(__float_as_uint(kb)));

            uint32_t srow = spec_base + (uint32_t)((tile * FT + ff) * (NCOL_PAD * 4));
            #pragma unroll
            for (int q = 0; q < 8; q++) {
                unsigned long long v01, v23;   // spec col pairs (4q,4q+1) and (4q+2,4q+3)
                asm volatile("ld.shared.v2.b64 {%0, %1}, [%2];"
                             : "=l"(v01), "=l"(v23) : "r"(srow + q * 16));
                FMA2(accK[2*q],     ka2, v01);
                FMA2(accB[2*q],     kb2, v01);
                FMA2(accK[2*q + 1], ka2, v23);
                FMA2(accB[2*q + 1], kb2, v23);
            }
            unsigned long long vt;             // tail pair: cols (32,33)
            asm volatile("ld.shared.b64 %0, [%1];" : "=l"(vt) : "r"(srow + 128));
            FMA2(accK[16], ka2, vt);
            FMA2(accB[16], kb2, vt);
        }
    }

    // ---- Epilogue: out seg s0+i = accK[j=i+1] + accB[j=i], scaled by 4/NFFT ----
    const float scale = 1.0f / 128.0f;
    float* outp = out + (size_t)b * L_OUT + (size_t)s0 * 256 + k;
    #pragma unroll
    for (int i = 0; i < NSEG; i++) {
        int s = s0 + i;
        if (s < NSEG_TOTAL) {
            int jk = i + 1;
            unsigned uK = (jk & 1) ? (unsigned)(accK[jk >> 1] >> 32)
                                   : (unsigned)(accK[jk >> 1]);
            unsigned uB = (i & 1)  ? (unsigned)(accB[i >> 1] >> 32)
                                   : (unsigned)(accB[i >> 1]);
            outp[(size_t)i * 256] = scale * (__uint_as_float(uK) + __uint_as_float(uB));
        }
    }
}

extern "C" void kernel_launch(void* const* d_in, const int* in_sizes, int n_in,
                              void* d_out, int out_size)
{
    const float* spec    = (const float*)d_in[0];   // [16,1,256,4096]
    const float* kernels = (const float*)d_in[1];   // [512,256]
    float* out = (float*)d_out;                     // [16,1048832]

    const int smem_bytes = (512 * KPAD + 256 * NCOL_PAD) * sizeof(float); // 104,448
    cudaFuncSetAttribute(imdct_fused_kernel,
                         cudaFuncAttributeMaxDynamicSharedMemorySize, smem_bytes);

    dim3 grid((NSEG_TOTAL + NSEG - 1) / NSEG, 16);  // (129, 16)
    imdct_fused_kernel<<<grid, 256, smem_bytes>>>(spec, kernels, out);
}

// round 2
// speedup vs baseline: 1.1412x; 1.1412x over previous
#include <cuda_runtime.h>
#include <cstdint>

// IMDCT fused:
//   out[b, s*256+k] = sum_f Ks[k,f]*spec[b,f,s] + sum_f Ks[k+256,f]*spec[b,f,s-1]
// with Ks = kernels/128 (scale folded into pre-transposed weights).
//
// Stage 1 (transpose_scale): kt2[f][k] = { kernels[k][f], kernels[k+256][f] } / 128
//   stored as float2, k-contiguous -> coalesced LDG.64 in the main loop, L2-resident (512KB).
// Stage 2 (main): block = 128 threads, each thread owns TWO output offsets (k=tid, k=tid+128)
//   and NSEG=32 segments. Spec columns s0-1..s0+32 live in smem; per f the uniform 16B spec
//   broadcast feeds 8 packed fma.rn.f32x2 (4 weight streams x 2 column-pairs).

#define NFREQ      256
#define T_FRAMES   4096
#define NSEG       32
#define NCOL_PAD   36          // 34 used cols (33 real + 1 zero), padded for 16B loads
#define L_OUT      1048832
#define NSEG_TOTAL 4097

#define FMA2(acc, a, v) \
    asm("fma.rn.f32x2 %0, %1, %2, %0;" : "+l"(acc) : "l"(a), "l"(v))
#define PACK2(dst, x) \
    asm("mov.b64 %0, {%1, %1};" : "=l"(dst) : "r"(__float_as_uint(x)))

// [257 rows x 256 float2] : one pad row so prefetch of row f=256 is in-bounds.
__device__ float2 g_kt2[257 * 256];

__global__ void transpose_scale_kernel(const float* __restrict__ kernels)
{
    int idx = blockIdx.x * blockDim.x + threadIdx.x;   // 65536 threads
    int f = idx & 255;                                 // coalesced read over f
    int k = idx >> 8;
    const float s = 1.0f / 128.0f;
    float2 w;
    w.x = s * kernels[k * 256 + f];
    w.y = s * kernels[(k + 256) * 256 + f];
    g_kt2[f * 256 + k] = w;
}

__global__ __launch_bounds__(128, 3)
void imdct_main_kernel(const float* __restrict__ spec, float* __restrict__ out)
{
    __shared__ float spec_sm[NFREQ * NCOL_PAD];        // 36,864 B

    const int tid = threadIdx.x;                       // 0..127
    const int b   = blockIdx.y;
    const int s0  = blockIdx.x * NSEG;

    // ---- Load spec columns c = s0-1 .. s0+32 (zero-fill edges / pad) ----
    const float* specB = spec + (size_t)b * NFREQ * T_FRAMES;
    for (int idx = tid; idx < NFREQ * NCOL_PAD; idx += 128) {
        int f = idx / NCOL_PAD;
        int j = idx - f * NCOL_PAD;
        int c = s0 - 1 + j;
        float v = 0.0f;
        if (j < 34 && c >= 0 && c < T_FRAMES)
            v = specB[(size_t)f * T_FRAMES + c];
        spec_sm[idx] = v;
    }
    __syncthreads();

    // ---- Accumulators: 17 column-pairs x 4 streams (k / k+128, each K-half / B-half) ----
    unsigned long long aK0[17], aB0[17], aK1[17], aB1[17];
    #pragma unroll
    for (int p = 0; p < 17; p++) { aK0[p] = 0ull; aB0[p] = 0ull; aK1[p] = 0ull; aB1[p] = 0ull; }

    const uint32_t sbase = (uint32_t)__cvta_generic_to_shared(spec_sm);
    const float2* __restrict__ w0p = g_kt2 + tid;          // weights for k = tid
    const float2* __restrict__ w1p = g_kt2 + tid + 128;    // weights for k = tid+128

    float2 w0 = w0p[0], w1 = w1p[0];                       // prefetch f = 0

    for (int f = 0; f < NFREQ; f++) {
        float2 nw0 = w0p[(f + 1) * 256];                   // prefetch f+1 (pad row at f=256)
        float2 nw1 = w1p[(f + 1) * 256];

        unsigned long long ka0, kb0, ka1, kb1;
        PACK2(ka0, w0.x); PACK2(kb0, w0.y);
        PACK2(ka1, w1.x); PACK2(kb1, w1.y);

        uint32_t srow = sbase + (uint32_t)(f * (NCOL_PAD * 4));
        #pragma unroll
        for (int q = 0; q < 8; q++) {
            unsigned long long v01, v23;                   // col pairs (4q,4q+1), (4q+2,4q+3)
            asm volatile("ld.shared.v2.b64 {%0, %1}, [%2];"
                         : "=l"(v01), "=l"(v23) : "r"(srow + q * 16));
            FMA2(aK0[2*q],     ka0, v01);  FMA2(aB0[2*q],     kb0, v01);
            FMA2(aK1[2*q],     ka1, v01);  FMA2(aB1[2*q],     kb1, v01);
            FMA2(aK0[2*q + 1], ka0, v23);  FMA2(aB0[2*q + 1], kb0, v23);
            FMA2(aK1[2*q + 1], ka1, v23);  FMA2(aB1[2*q + 1], kb1, v23);
        }
        unsigned long long vt;                             // tail pair: cols (32,33)
        asm volatile("ld.shared.b64 %0, [%1];" : "=l"(vt) : "r"(srow + 128));
        FMA2(aK0[16], ka0, vt);  FMA2(aB0[16], kb0, vt);
        FMA2(aK1[16], ka1, vt);  FMA2(aB1[16], kb1, vt);

        w0 = nw0; w1 = nw1;
    }

    // ---- Epilogue: seg s0+i gets accK[j=i+1] + accB[j=i] ----
    float* o0 = out + (size_t)b * L_OUT + (size_t)s0 * 256 + tid;
    #pragma unroll
    for (int i = 0; i < NSEG; i++) {
        int s = s0 + i;
        if (s < NSEG_TOTAL) {
            int jk = i + 1;
            unsigned uK0 = (jk & 1) ? (unsigned)(aK0[jk >> 1] >> 32) : (unsigned)aK0[jk >> 1];
            unsigned uB0 = (i  & 1) ? (unsigned)(aB0[i  >> 1] >> 32) : (unsigned)aB0[i  >> 1];
            unsigned uK1 = (jk & 1) ? (unsigned)(aK1[jk >> 1] >> 32) : (unsigned)aK1[jk >> 1];
            unsigned uB1 = (i  & 1) ? (unsigned)(aB1[i  >> 1] >> 32) : (unsigned)aB1[i  >> 1];
            o0[(size_t)i * 256]       = __uint_as_float(uK0) + __uint_as_float(uB0);
            o0[(size_t)i * 256 + 128] = __uint_as_float(uK1) + __uint_as_float(uB1);
        }
    }
}

extern "C" void kernel_launch(void* const* d_in, const int* in_sizes, int n_in,
                              void* d_out, int out_size)
{
    const float* spec    = (const float*)d_in[0];   // [16,1,256,4096]
    const float* kernels = (const float*)d_in[1];   // [512,256]
    float* out = (float*)d_out;                     // [16,1048832]

    transpose_scale_kernel<<<256, 256>>>(kernels);  // 65536 threads

    dim3 grid((NSEG_TOTAL + NSEG - 1) / NSEG, 16);  // (129, 16)
    imdct_main_kernel<<<grid, 128>>>(spec, out);
}